// round 16
// baseline (speedup 1.0000x reference)
#include <cuda_runtime.h>
#include <cuda_bf16.h>
#include <cstdint>

// Correlation volume as banded GEMM on HMMA (mma.sync m16n8k16 bf16).
// CTA tile: 16x8 px (M=128). Halo: 24x16 (N=384). K = Z = 128.
// D[m,n] = sum_z A[z,m]*B[z,n]; bf16 hi/lo split: AhBh + AhBl + AlBh.
// Warp w owns pixel row py=w -> band n in [24w, 24w+216) = 27 n-blocks.

#define Nn   8
#define Zz   128
#define Hh   160
#define Ww   160
#define TPX  16
#define TPY  8
#define AS   272          // A smem row bytes: 128 bf16 + pad (banks 4g+tig)
#define BS   48           // B smem row bytes: 16 bf16 + pad (banks 12g+tig)
#define AH_OFF 0
#define AL_OFF 34816      // 128*272
#define BH_OFF 69632
#define BL_OFF 88064      // +384*48
#define DSTR 880          // D smem row bytes (220 words)
#define DWARP 14080       // 16*880
#define SMEM_BYTES 112640 // 8*DWARP (covers A+B region too)

__device__ __forceinline__ void split2(float x, float y, uint32_t& h, uint32_t& l) {
    __nv_bfloat16 hx = __float2bfloat16_rn(x);
    __nv_bfloat16 hy = __float2bfloat16_rn(y);
    union { __nv_bfloat162 v; uint32_t u; } ch, cl;
    ch.v.x = hx; ch.v.y = hy;
    cl.v.x = __float2bfloat16_rn(x - __bfloat162float(hx));
    cl.v.y = __float2bfloat16_rn(y - __bfloat162float(hy));
    h = ch.u; l = cl.u;
}

__global__ __launch_bounds__(256, 1)
void corr_mma_kernel(const float* __restrict__ A,
                     const float* __restrict__ B,
                     float* __restrict__ out)
{
    extern __shared__ char SM[];
    const int tid  = threadIdx.x;
    const int lane = tid & 31;
    const int wrp  = tid >> 5;        // 0..7 == pixel row py
    const int g    = lane >> 2;       // groupID
    const int tig  = lane & 3;        // thread-in-group

    const int w0 = blockIdx.x * TPX;
    const int h0 = blockIdx.y * TPY;
    const int n  = blockIdx.z;
    const size_t plane = (size_t)Hh * Ww;

    // ---------------- A fill (resident, hi/lo bf16) ----------------
    {
        const int px = tid & 15, py = (tid >> 4) & 7, zg = tid >> 7;
        const float* gp = A + ((size_t)n * Zz + zg * 64) * plane
                            + (size_t)(h0 + py) * Ww + (w0 + px);
        char* ah = SM + AH_OFF + (size_t)(py * 16 + px) * AS + zg * 128;
        char* al = SM + AL_OFF + (size_t)(py * 16 + px) * AS + zg * 128;
        #pragma unroll 1
        for (int blk = 0; blk < 8; blk++) {
            float v[8];
            #pragma unroll
            for (int u = 0; u < 8; u++) v[u] = gp[(size_t)(blk * 8 + u) * plane];
            uint32_t hh[4], ll[4];
            #pragma unroll
            for (int p = 0; p < 4; p++) split2(v[2*p], v[2*p+1], hh[p], ll[p]);
            *(uint4*)(ah + blk * 16) = make_uint4(hh[0], hh[1], hh[2], hh[3]);
            *(uint4*)(al + blk * 16) = make_uint4(ll[0], ll[1], ll[2], ll[3]);
        }
    }

    // ---------------- B fill roles (384 halo rows, 2 slots) ----------------
    const int hx0 = tid % 24, hy0 = tid / 24;
    const int gh0 = h0 - 4 + hy0, gw0 = w0 - 4 + hx0;
    const bool val0 = ((unsigned)gh0 < Hh) && ((unsigned)gw0 < Ww);
    const float* bgp0 = B + (size_t)n * Zz * plane
                          + (size_t)(val0 ? gh0 : 0) * Ww + (val0 ? gw0 : 0);
    const bool has1 = tid < 128;
    const int hp1 = 256 + tid;
    const int hx1 = hp1 % 24, hy1 = hp1 / 24;
    const int gh1 = h0 - 4 + hy1, gw1 = w0 - 4 + hx1;
    const bool val1 = has1 && ((unsigned)gh1 < Hh) && ((unsigned)gw1 < Ww);
    const float* bgp1 = B + (size_t)n * Zz * plane
                          + (size_t)(val1 ? gh1 : 0) * Ww + (val1 ? gw1 : 0);

    float s0[16], s1[16];
    auto stage = [&](int kc) {
        const size_t zo = (size_t)kc * 16 * plane;
        #pragma unroll
        for (int u = 0; u < 16; u++) s0[u] = val0 ? bgp0[zo + u * plane] : 0.f;
        if (has1) {
            #pragma unroll
            for (int u = 0; u < 16; u++) s1[u] = val1 ? bgp1[zo + u * plane] : 0.f;
        }
    };
    auto commit = [&]() {
        uint32_t hh[8], ll[8];
        #pragma unroll
        for (int p = 0; p < 8; p++) split2(s0[2*p], s0[2*p+1], hh[p], ll[p]);
        char* bh = SM + BH_OFF + (size_t)tid * BS;
        char* bl = SM + BL_OFF + (size_t)tid * BS;
        *(uint4*)(bh)      = make_uint4(hh[0], hh[1], hh[2], hh[3]);
        *(uint4*)(bh + 16) = make_uint4(hh[4], hh[5], hh[6], hh[7]);
        *(uint4*)(bl)      = make_uint4(ll[0], ll[1], ll[2], ll[3]);
        *(uint4*)(bl + 16) = make_uint4(ll[4], ll[5], ll[6], ll[7]);
        if (has1) {
            #pragma unroll
            for (int p = 0; p < 8; p++) split2(s1[2*p], s1[2*p+1], hh[p], ll[p]);
            char* bh1 = SM + BH_OFF + (size_t)hp1 * BS;
            char* bl1 = SM + BL_OFF + (size_t)hp1 * BS;
            *(uint4*)(bh1)      = make_uint4(hh[0], hh[1], hh[2], hh[3]);
            *(uint4*)(bh1 + 16) = make_uint4(hh[4], hh[5], hh[6], hh[7]);
            *(uint4*)(bl1)      = make_uint4(ll[0], ll[1], ll[2], ll[3]);
            *(uint4*)(bl1 + 16) = make_uint4(ll[4], ll[5], ll[6], ll[7]);
        }
    };

    // ---------------- accumulators ----------------
    float acc[27][4];
    #pragma unroll
    for (int nb = 0; nb < 27; nb++)
        #pragma unroll
        for (int c = 0; c < 4; c++) acc[nb][c] = 0.f;

    // ---------------- main loop over 8 k-chunks ----------------
    stage(0);
    #pragma unroll 1
    for (int kc = 0; kc < 8; kc++) {
        __syncthreads();              // prior MMA done: B buffer writable (also A ready, kc=0)
        commit();
        __syncthreads();              // B chunk visible
        if (kc < 7) stage(kc + 1);    // LDG latency hidden under MMA below

        #pragma unroll 1
        for (int sp = 0; sp < 3; sp++) {
            const char* ab = SM + (sp == 2 ? AL_OFF : AH_OFF)
                           + (size_t)(wrp * 16 + g) * AS + kc * 32 + tig * 4;
            const char* bb = SM + (sp == 1 ? BL_OFF : BH_OFF)
                           + (size_t)(24 * wrp + g) * BS + tig * 4;
            const uint32_t a0 = *(const uint32_t*)(ab);
            const uint32_t a1 = *(const uint32_t*)(ab + 8 * AS);
            const uint32_t a2 = *(const uint32_t*)(ab + 16);
            const uint32_t a3 = *(const uint32_t*)(ab + 8 * AS + 16);
            #pragma unroll
            for (int nb = 0; nb < 27; nb++) {
                const uint32_t b0 = *(const uint32_t*)(bb + nb * 8 * BS);
                const uint32_t b1 = *(const uint32_t*)(bb + nb * 8 * BS + 16);
                asm volatile(
                    "mma.sync.aligned.m16n8k16.row.col.f32.bf16.bf16.f32 "
                    "{%0,%1,%2,%3}, {%4,%5,%6,%7}, {%8,%9}, {%0,%1,%2,%3};"
                    : "+f"(acc[nb][0]), "+f"(acc[nb][1]),
                      "+f"(acc[nb][2]), "+f"(acc[nb][3])
                    : "r"(a0), "r"(a1), "r"(a2), "r"(a3), "r"(b0), "r"(b1));
            }
        }
    }

    // ---------------- epilogue: D -> smem -> banded gather -> out ----------------
    __syncthreads();                  // all MMA done before D overwrites A/B smem
    char* Dw = SM + (size_t)wrp * DWARP;
    #pragma unroll
    for (int nb = 0; nb < 27; nb++) {
        const int nl = nb * 8 + 2 * tig;
        *(float2*)(Dw + (size_t)g * DSTR + nl * 4)       = make_float2(acc[nb][0], acc[nb][1]);
        *(float2*)(Dw + (size_t)(g + 8) * DSTR + nl * 4) = make_float2(acc[nb][2], acc[nb][3]);
    }
    __syncwarp();

    // D element (px, nl = 24j + i + px) -> out[k=9i+j][h0+wrp][w0+px]
    float* ob = out + (size_t)n * 81 * plane + (size_t)(h0 + wrp) * Ww + w0;
    #pragma unroll 1
    for (int t = lane; t < 324; t += 32) {
        const int k = t >> 2, q = t & 3;
        const int i = k / 9, j = k - 9 * i;
        const char* dp = Dw + (size_t)(4 * q) * (DSTR + 4) + (24 * j + i) * 4;
        const float f0 = *(const float*)(dp);
        const float f1 = *(const float*)(dp + (DSTR + 4));
        const float f2 = *(const float*)(dp + 2 * (DSTR + 4));
        const float f3 = *(const float*)(dp + 3 * (DSTR + 4));
        *(float4*)(ob + (size_t)k * plane + 4 * q) = make_float4(f0, f1, f2, f3);
    }
}

extern "C" void kernel_launch(void* const* d_in, const int* in_sizes, int n_in,
                              void* d_out, int out_size)
{
    const float* imgA = (const float*)d_in[0];
    const float* imgB = (const float*)d_in[1];
    float* out = (float*)d_out;

    cudaFuncSetAttribute(corr_mma_kernel,
                         cudaFuncAttributeMaxDynamicSharedMemorySize, SMEM_BYTES);

    dim3 grid(Ww / TPX, Hh / TPY, Nn);   // 10 x 20 x 8 = 1600 CTAs
    corr_mma_kernel<<<grid, 256, SMEM_BYTES>>>(imgA, imgB, out);
}

// round 17
// speedup vs baseline: 1.0755x; 1.0755x over previous
#include <cuda_runtime.h>
#include <cuda_bf16.h>
#include <cstdint>

// Correlation volume as banded GEMM on HMMA (mma.sync m16n8k16 bf16).
// CTA tile: 16x8 px (M=128). Halo: 24x16 (N=384). K = Z = 128.
// D[m,n] = sum_z A[z,m]*B[z,n]; bf16 hi/lo split: AhBh + AhBl + AlBh.
// 512 threads: warp (r, half) = pixel row r (0..7), half-band of 14/13
// n-blocks -> acc 56 regs, 16 warps resident. B double-buffered, one
// barrier per k-chunk; stage LDGs issued before MMA to hide gmem latency.

#define Nn   8
#define Zz   128
#define Hh   160
#define Ww   160
#define TPX  16
#define TPY  8
#define NT   512
#define AS   272            // A smem row bytes (128 bf16 + pad)
#define BSr  48             // B smem row bytes (16 bf16 + pad)
#define AH_OFF 0
#define AL_OFF 34816        // 128*272
#define BBASE  69632
#define BBUF   36864        // hi(18432) + lo(18432) per buffer
#define DSTR 880            // D row bytes (220 words)
#define DWARP 14080         // 16*DSTR
#define SMEM_BYTES (BBASE + 2 * BBUF)   // 143360

__device__ __forceinline__ void split2(float x, float y, uint32_t& h, uint32_t& l) {
    __nv_bfloat16 hx = __float2bfloat16_rn(x);
    __nv_bfloat16 hy = __float2bfloat16_rn(y);
    union { __nv_bfloat162 v; uint32_t u; } ch, cl;
    ch.v.x = hx; ch.v.y = hy;
    cl.v.x = __float2bfloat16_rn(x - __bfloat162float(hx));
    cl.v.y = __float2bfloat16_rn(y - __bfloat162float(hy));
    h = ch.u; l = cl.u;
}

__global__ __launch_bounds__(NT, 1)
void corr_mma_kernel(const float* __restrict__ A,
                     const float* __restrict__ B,
                     float* __restrict__ out)
{
    extern __shared__ char SM[];
    const int tid  = threadIdx.x;
    const int lane = tid & 31;
    const int wrp  = tid >> 5;        // 0..15
    const int r    = wrp >> 1;        // pixel row 0..7
    const int half = wrp & 1;         // band half
    const int g    = lane >> 2;       // groupID
    const int tig  = lane & 3;        // thread-in-group

    const int nb0 = half ? 14 : 0;    // first n-block (global)
    const int nbn = half ? 13 : 14;   // count

    const int w0 = blockIdx.x * TPX;
    const int h0 = blockIdx.y * TPY;
    const int n  = blockIdx.z;
    const size_t plane = (size_t)Hh * Ww;

    // ---------------- A fill (resident, hi/lo bf16): 512 threads ----------------
    {
        const int ar = tid >> 2;            // A row 0..127 (= py*16+px)
        const int zq = tid & 3;             // z quarter: z in [32zq, 32zq+32)
        const int px = ar & 15, py = ar >> 4;
        const float* gp = A + ((size_t)n * Zz + 32 * zq) * plane
                            + (size_t)(h0 + py) * Ww + (w0 + px);
        char* ah = SM + AH_OFF + (size_t)ar * AS + zq * 64;
        char* al = SM + AL_OFF + (size_t)ar * AS + zq * 64;
        #pragma unroll 1
        for (int blk = 0; blk < 4; blk++) {
            float v[8];
            #pragma unroll
            for (int u = 0; u < 8; u++) v[u] = gp[(size_t)(blk * 8 + u) * plane];
            uint32_t hh[4], ll[4];
            #pragma unroll
            for (int p = 0; p < 4; p++) split2(v[2*p], v[2*p+1], hh[p], ll[p]);
            *(uint4*)(ah + blk * 16) = make_uint4(hh[0], hh[1], hh[2], hh[3]);
            *(uint4*)(al + blk * 16) = make_uint4(ll[0], ll[1], ll[2], ll[3]);
        }
    }

    // ---------------- B fill role: one halo row per thread (tid < 384) --------
    const bool bfill = tid < 384;
    const int hx = tid % 24, hy = tid / 24;
    const int gh = h0 - 4 + hy, gw = w0 - 4 + hx;
    const bool bval = bfill && ((unsigned)gh < Hh) && ((unsigned)gw < Ww);
    const float* bgp = B + (size_t)n * Zz * plane
                         + (size_t)(bval ? gh : 0) * Ww + (bval ? gw : 0);

    float s0[16];
    auto stage = [&](int kc) {
        if (!bfill) return;
        const size_t zo = (size_t)kc * 16 * plane;
        #pragma unroll
        for (int u = 0; u < 16; u++) s0[u] = bval ? bgp[zo + u * plane] : 0.f;
    };
    auto commit = [&](int buf) {
        if (!bfill) return;
        uint32_t hh[8], ll[8];
        #pragma unroll
        for (int p = 0; p < 8; p++) split2(s0[2*p], s0[2*p+1], hh[p], ll[p]);
        char* bh = SM + BBASE + buf * BBUF + (size_t)tid * BSr;
        char* bl = bh + 18432;
        *(uint4*)(bh)      = make_uint4(hh[0], hh[1], hh[2], hh[3]);
        *(uint4*)(bh + 16) = make_uint4(hh[4], hh[5], hh[6], hh[7]);
        *(uint4*)(bl)      = make_uint4(ll[0], ll[1], ll[2], ll[3]);
        *(uint4*)(bl + 16) = make_uint4(ll[4], ll[5], ll[6], ll[7]);
    };

    // ---------------- accumulators: 14 n-blocks max ----------------
    float acc[14][4];
    #pragma unroll
    for (int nb = 0; nb < 14; nb++)
        #pragma unroll
        for (int c = 0; c < 4; c++) acc[nb][c] = 0.f;

    // ---------------- main loop: 8 k-chunks, double-buffered B ----------------
    stage(0);
    commit(0);
    __syncthreads();                          // buf0 + A visible

    #pragma unroll 1
    for (int kc = 0; kc < 8; kc++) {
        if (kc < 7) stage(kc + 1);            // LDGs in flight during MMA

        #pragma unroll 1
        for (int sp = 0; sp < 3; sp++) {
            const char* ab = SM + (sp == 2 ? AL_OFF : AH_OFF)
                           + (size_t)(r * 16 + g) * AS + kc * 32 + tig * 4;
            const uint32_t a0 = *(const uint32_t*)(ab);
            const uint32_t a1 = *(const uint32_t*)(ab + 8 * AS);
            const uint32_t a2 = *(const uint32_t*)(ab + 16);
            const uint32_t a3 = *(const uint32_t*)(ab + 8 * AS + 16);
            const char* bb = SM + BBASE + (kc & 1) * BBUF + (sp == 1 ? 18432 : 0)
                           + (size_t)(24 * r + nb0 * 8 + g) * BSr + tig * 4;
            #pragma unroll
            for (int nb = 0; nb < 14; nb++) {
                if (nb < nbn) {
                    const uint32_t b0 = *(const uint32_t*)(bb + nb * 8 * BSr);
                    const uint32_t b1 = *(const uint32_t*)(bb + nb * 8 * BSr + 16);
                    asm volatile(
                        "mma.sync.aligned.m16n8k16.row.col.f32.bf16.bf16.f32 "
                        "{%0,%1,%2,%3}, {%4,%5,%6,%7}, {%8,%9}, {%0,%1,%2,%3};"
                        : "+f"(acc[nb][0]), "+f"(acc[nb][1]),
                          "+f"(acc[nb][2]), "+f"(acc[nb][3])
                        : "r"(a0), "r"(a1), "r"(a2), "r"(a3), "r"(b0), "r"(b1));
                }
            }
        }

        if (kc < 7) commit((kc + 1) & 1);     // overwrites chunk kc-1's buffer (safe)
        __syncthreads();
    }

    // ---------------- epilogue: D -> smem -> banded gather -> out -------------
    char* Dw = SM + (size_t)r * DWARP;        // per-row 16x220 fp32 region
    #pragma unroll
    for (int nb = 0; nb < 14; nb++) {
        if (nb < nbn) {
            const int nl = (nb0 + nb) * 8 + 2 * tig;
            *(float2*)(Dw + (size_t)g * DSTR + nl * 4)       = make_float2(acc[nb][0], acc[nb][1]);
            *(float2*)(Dw + (size_t)(g + 8) * DSTR + nl * 4) = make_float2(acc[nb][2], acc[nb][3]);
        }
    }
    __syncthreads();

    // D element (px, 24j + i + px) -> out[k=9i+j][h0+r][w0+px]; 64 lanes per row
    float* ob = out + (size_t)n * 81 * plane + (size_t)(h0 + r) * Ww + w0;
    #pragma unroll 1
    for (int t = lane + 32 * half; t < 324; t += 64) {
        const int k = t >> 2, q = t & 3;
        const int i = k / 9, j = k - 9 * i;
        const char* dp = Dw + (size_t)(4 * q) * (DSTR + 4) + (24 * j + i) * 4;
        const float f0 = *(const float*)(dp);
        const float f1 = *(const float*)(dp + (DSTR + 4));
        const float f2 = *(const float*)(dp + 2 * (DSTR + 4));
        const float f3 = *(const float*)(dp + 3 * (DSTR + 4));
        *(float4*)(ob + (size_t)k * plane + 4 * q) = make_float4(f0, f1, f2, f3);
    }
}

extern "C" void kernel_launch(void* const* d_in, const int* in_sizes, int n_in,
                              void* d_out, int out_size)
{
    const float* imgA = (const float*)d_in[0];
    const float* imgB = (const float*)d_in[1];
    float* out = (float*)d_out;

    cudaFuncSetAttribute(corr_mma_kernel,
                         cudaFuncAttributeMaxDynamicSharedMemorySize, SMEM_BYTES);

    dim3 grid(Ww / TPX, Hh / TPY, Nn);   // 10 x 20 x 8 = 1600 CTAs
    corr_mma_kernel<<<grid, NT, SMEM_BYTES>>>(imgA, imgB, out);
}